// round 1
// baseline (speedup 1.0000x reference)
#include <cuda_runtime.h>
#include <cstdint>

#define ROW_LEN 4096
#define K_TOP   64
#define THREADS 512
#define EPT     8   // elements per thread

__device__ __forceinline__ uint32_t f2k(float f) {
    uint32_t u = __float_as_uint(f);
    return (u & 0x80000000u) ? ~u : (u | 0x80000000u);
}
__device__ __forceinline__ float k2f(uint32_t k) {
    uint32_t u = (k & 0x80000000u) ? (k ^ 0x80000000u) : ~k;
    return __uint_as_float(u);
}

__global__ __launch_bounds__(THREADS, 2)
void topk_mask_kernel(const float* __restrict__ x, float* __restrict__ out) {
    const int row = blockIdx.x;
    const int tid = threadIdx.x;
    const int lane = tid & 31;
    const int wid  = tid >> 5;

    const float4* xrow = reinterpret_cast<const float4*>(x + (size_t)row * ROW_LEN);
    float4*       orow = reinterpret_cast<float4*>(out + (size_t)row * ROW_LEN);

    // Thread t owns contiguous elements [8t, 8t+8): vec indices 2t, 2t+1.
    // Streaming loads (data read exactly once).
    float4 v0 = __ldcs(&xrow[2 * tid]);
    float4 v1 = __ldcs(&xrow[2 * tid + 1]);

    uint32_t keys[EPT];
    keys[0] = f2k(v0.x); keys[1] = f2k(v0.y); keys[2] = f2k(v0.z); keys[3] = f2k(v0.w);
    keys[4] = f2k(v1.x); keys[5] = f2k(v1.y); keys[6] = f2k(v1.z); keys[7] = f2k(v1.w);

    __shared__ uint32_t hist[256];
    __shared__ uint32_t sS[256];      // inclusive-from-top suffix sums
    __shared__ uint32_t s_sel[2];     // [0]=selected bin, [1]=new rem
    __shared__ uint32_t warp_sums[16];

    uint32_t prefix = 0;
    uint32_t rem = K_TOP;

    // ---- 4-pass radix select (MSB -> LSB, 8 bits each) ----
    #pragma unroll
    for (int pass = 0; pass < 4; ++pass) {
        const int shift = 24 - 8 * pass;
        const uint32_t hm = (pass == 0) ? 0u : (~0u << (shift + 8));

        if (tid < 256) hist[tid] = 0;
        __syncthreads();

        // warp-aggregated histogram over candidates matching the current prefix
        #pragma unroll
        for (int j = 0; j < EPT; ++j) {
            bool pred = ((keys[j] & hm) == prefix);
            if (pred) {
                uint32_t bin = (keys[j] >> shift) & 0xFFu;
                unsigned peers = __match_any_sync(__activemask(), bin);
                int leader = __ffs(peers) - 1;
                if (lane == leader)
                    atomicAdd(&hist[bin], (uint32_t)__popc(peers));
            }
        }
        __syncthreads();

        // warp 0 computes suffix sums S[b] = sum_{j>=b} hist[j]
        if (tid < 32) {
            uint32_t local[8];
            uint32_t s = 0;
            #pragma unroll
            for (int j = 0; j < 8; ++j) {
                int b = 255 - (tid * 8 + j);
                s += hist[b];
                local[j] = s;                 // inclusive-from-top within lane
            }
            uint32_t incl = s;                // scan lane totals
            #pragma unroll
            for (int off = 1; off < 32; off <<= 1) {
                uint32_t n = __shfl_up_sync(0xffffffffu, incl, off);
                if (tid >= off) incl += n;
            }
            uint32_t excl = incl - s;
            #pragma unroll
            for (int j = 0; j < 8; ++j) {
                int b = 255 - (tid * 8 + j);
                sS[b] = excl + local[j];
            }
        }
        __syncthreads();

        // select bin b: S[b] >= rem > S[b+1]
        if (tid < 256) {
            uint32_t above = (tid == 255) ? 0u : sS[tid + 1];
            if (sS[tid] >= rem && above < rem) {
                s_sel[0] = (uint32_t)tid;
                s_sel[1] = rem - above;
            }
        }
        __syncthreads();

        prefix |= s_sel[0] << shift;
        rem = s_sel[1];
        __syncthreads();   // protect s_sel before next pass rewrites it
    }

    const uint32_t T = prefix;   // exact k-th largest key
    // rem = how many T-equal elements (in increasing index order) to include

    // ---- exact tie ordering: block exclusive scan of per-thread equal counts,
    //      thread order == global index order (contiguous ownership) ----
    uint32_t cnt = 0;
    #pragma unroll
    for (int j = 0; j < EPT; ++j) cnt += (keys[j] == T);

    uint32_t incl = cnt;
    #pragma unroll
    for (int off = 1; off < 32; off <<= 1) {
        uint32_t n = __shfl_up_sync(0xffffffffu, incl, off);
        if (lane >= off) incl += n;
    }
    if (lane == 31) warp_sums[wid] = incl;
    __syncthreads();
    if (tid < 16) {
        uint32_t v = warp_sums[tid];
        #pragma unroll
        for (int off = 1; off < 16; off <<= 1) {
            uint32_t n = __shfl_up_sync(0xffffu, v, off);
            if (tid >= off) v += n;
        }
        warp_sums[tid] = v;   // inclusive warp prefix
    }
    __syncthreads();
    uint32_t base = ((wid > 0) ? warp_sums[wid - 1] : 0u) + (incl - cnt);

    // ---- masked write ----
    float o[EPT];
    uint32_t r = base;
    #pragma unroll
    for (int j = 0; j < EPT; ++j) {
        bool inc;
        if (keys[j] > T) {
            inc = true;
        } else if (keys[j] == T) {
            inc = (r < rem);
            r++;
        } else {
            inc = false;
        }
        o[j] = inc ? k2f(keys[j]) : 0.0f;
    }
    float4 w0 = make_float4(o[0], o[1], o[2], o[3]);
    float4 w1 = make_float4(o[4], o[5], o[6], o[7]);
    __stcs(&orow[2 * tid],     w0);
    __stcs(&orow[2 * tid + 1], w1);
}

extern "C" void kernel_launch(void* const* d_in, const int* in_sizes, int n_in,
                              void* d_out, int out_size) {
    const float* x = (const float*)d_in[0];
    float* out = (float*)d_out;
    int rows = in_sizes[0] / ROW_LEN;
    topk_mask_kernel<<<rows, THREADS>>>(x, out);
}